// round 6
// baseline (speedup 1.0000x reference)
#include <cuda_runtime.h>
#include <cstdint>

#define Bn 8
#define Cn 64
#define Hn 256
#define Wn 256
#define TM 64
#define NTH 512
#define NCH 16          // 256 / 16 k per chunk

// smem byte offsets
#define XH_OFF 0        // x hi  [64][256] permuted, 64KB
#define XL_OFF 65536    // x lo, 64KB
#define B_OFF  131072   // 3 stages x 32KB (hi 16KB + lo 16KB), [256 n][16 k perm]
#define B_STRIDE 32768
#define B_LO   16384
#define RED_OFF 229376  // [64][8] floats
#define SM_TOTAL 231424

typedef uint4 U4;

__device__ __forceinline__ void sts128(uint32_t a, uint32_t x, uint32_t y, uint32_t z, uint32_t w) {
    asm volatile("st.shared.v4.b32 [%0],{%1,%2,%3,%4};" :: "r"(a), "r"(x), "r"(y), "r"(z), "r"(w));
}
__device__ __forceinline__ void sts32(uint32_t a, uint32_t v) {
    asm volatile("st.shared.b32 [%0],%1;" :: "r"(a), "r"(v));
}
__device__ __forceinline__ U4 lds128(uint32_t a) {
    U4 r;
    asm volatile("ld.shared.v4.b32 {%0,%1,%2,%3},[%4];"
                 : "=r"(r.x), "=r"(r.y), "=r"(r.z), "=r"(r.w) : "r"(a));
    return r;
}
__device__ __forceinline__ uint32_t tf32c(float f) {
    uint32_t r; asm("cvt.rna.tf32.f32 %0,%1;" : "=r"(r) : "f"(f)); return r;
}
__device__ __forceinline__ void mma8(float* c,
    uint32_t a0, uint32_t a1, uint32_t a2, uint32_t a3, uint32_t b0, uint32_t b1) {
    asm volatile(
        "mma.sync.aligned.m16n8k8.row.col.f32.tf32.tf32.f32 "
        "{%0,%1,%2,%3},{%4,%5,%6,%7},{%8,%9},{%0,%1,%2,%3};"
        : "+f"(c[0]), "+f"(c[1]), "+f"(c[2]), "+f"(c[3])
        : "r"(a0), "r"(a1), "r"(a2), "r"(a3), "r"(b0), "r"(b1));
}

// ---------------------------------------------------------------------------
// One 64x256x256 GEMM in 3xTF32: acc[nt*4+ci] = D[row][col], warp tile 16x64.
// A (x) pre-split in smem (XH/XL). B (W) streamed: ldg 2 chunks ahead,
// transpose+split+STS 1 chunk ahead, 3-stage ring.
// ---------------------------------------------------------------------------
__device__ __forceinline__ void gemm_tf32(float acc[32], const float* __restrict__ wg,
                                          uint32_t sm, int tid, int lane, int wm, int wn)
{
    #pragma unroll
    for (int i = 0; i < 32; ++i) acc[i] = 0.f;

    const int m = lane & 3, g = lane >> 2;
    const int fm = tid & 3, fn0 = tid >> 2;   // fill: n = u*128 + fn0, k-residue fm
    float rb[2][8];

    auto LDG = [&](float* rr, int cc) {
        #pragma unroll
        for (int u = 0; u < 2; ++u) {
            const float* p = wg + (size_t)(cc * 16 + fm) * Wn + u * 128 + fn0;
            #pragma unroll
            for (int i = 0; i < 4; ++i)
                rr[u * 4 + i] = p[(size_t)(4 * i) * Wn];   // k = cc*16 + fm + 4i
        }
    };
    auto STS = [&](const float* rr, int cc) {
        const uint32_t st = sm + B_OFF + (uint32_t)(cc % 3) * B_STRIDE;
        #pragma unroll
        for (int u = 0; u < 2; ++u) {
            uint32_t h[4], l[4];
            #pragma unroll
            for (int i = 0; i < 4; ++i) {
                h[i] = tf32c(rr[u * 4 + i]);
                l[i] = tf32c(rr[u * 4 + i] - __uint_as_float(h[i]));
            }
            const uint32_t a = st + (uint32_t)((u * 128 + fn0) * 64 + fm * 16);
            sts128(a,        h[0], h[1], h[2], h[3]);
            sts128(a + B_LO, l[0], l[1], l[2], l[3]);
        }
    };

    LDG(rb[0], 0);
    LDG(rb[1], 1);
    STS(rb[0], 0);
    __syncthreads();

    const int r0 = wm * 16 + g;
    const uint32_t axor = (uint32_t)((r0 & 1) * 64);
    const uint32_t ah_base  = sm + XH_OFF + (uint32_t)(r0 * 1024);
    const uint32_t ah8_base = ah_base + 8 * 1024;
    const uint32_t al_base  = sm + XL_OFF + (uint32_t)(r0 * 1024);
    const uint32_t al8_base = al_base + 8 * 1024;
    const uint32_t bcol = (uint32_t)((wn * 64 + g) * 64 + m * 16);

    #pragma unroll 1
    for (int cc = 0; cc < NCH; ++cc) {
        if (cc + 2 < NCH) LDG(rb[cc & 1], cc + 2);
        {
            const uint32_t ao = ((uint32_t)(cc * 64 + m * 16)) ^ axor;
            U4 ahr  = lds128(ah_base  + ao);
            U4 ahr8 = lds128(ah8_base + ao);
            U4 alr  = lds128(al_base  + ao);
            U4 alr8 = lds128(al8_base + ao);
            const uint32_t bb = sm + B_OFF + (uint32_t)(cc % 3) * B_STRIDE + bcol;
            #pragma unroll
            for (int nt = 0; nt < 8; ++nt) {
                U4 bh = lds128(bb + nt * 512);
                U4 bl = lds128(bb + nt * 512 + B_LO);
                float* a4 = acc + nt * 4;
                mma8(a4, ahr.x, ahr8.x, ahr.y, ahr8.y, bh.x, bh.y);
                mma8(a4, ahr.z, ahr8.z, ahr.w, ahr8.w, bh.z, bh.w);
                mma8(a4, ahr.x, ahr8.x, ahr.y, ahr8.y, bl.x, bl.y);
                mma8(a4, ahr.z, ahr8.z, ahr.w, ahr8.w, bl.z, bl.w);
                mma8(a4, alr.x, alr8.x, alr.y, alr8.y, bh.x, bh.y);
                mma8(a4, alr.z, alr8.z, alr.w, alr8.w, bh.z, bh.w);
            }
        }
        if (cc + 1 < NCH) STS(rb[(cc + 1) & 1], cc + 1);
        __syncthreads();
    }
}

extern __shared__ float smem_dyn[];

__global__ void __launch_bounds__(NTH, 1) axile_attn_mma(
    const float* __restrict__ x,  const float* __restrict__ qw,
    const float* __restrict__ kw, const float* __restrict__ vw,
    const float* __restrict__ qb, const float* __restrict__ kb,
    const float* __restrict__ vb, float* __restrict__ out)
{
    const int tid  = threadIdx.x;
    const int lane = tid & 31;
    const int wid  = tid >> 5;
    const int wm   = wid & 3;
    const int wn   = wid >> 2;
    const int h0   = blockIdx.x * TM;
    const int ch   = blockIdx.y;
    const int b    = blockIdx.z;

    const uint32_t sm = (uint32_t)__cvta_generic_to_shared(smem_dyn);
    float* red = reinterpret_cast<float*>(reinterpret_cast<char*>(smem_dyn) + RED_OFF);

    // ---- fill x hi/lo into permuted smem (once) ----
    {
        const float* xg = x + ((size_t)((b * Cn + ch) * Hn + h0)) * Wn;
        #pragma unroll
        for (int it = 0; it < 8; ++it) {
            const int idx = tid + it * NTH;       // float4 index: 64 rows x 64
            const int r  = idx >> 6;
            const int j4 = idx & 63;
            float4 v = reinterpret_cast<const float4*>(xg)[(size_t)r * 64 + j4];
            const float f[4] = {v.x, v.y, v.z, v.w};
            const uint32_t rx = (uint32_t)((r & 1) * 16);
            #pragma unroll
            for (int s = 0; s < 4; ++s) {
                const int k = j4 * 4 + s;
                const uint32_t pos = ((uint32_t)((k >> 4) * 16 + s * 4 + (j4 & 3))) ^ rx;
                const uint32_t hi = tf32c(f[s]);
                const uint32_t lo = tf32c(f[s] - __uint_as_float(hi));
                sts32(sm + XH_OFF + (uint32_t)(r * 1024) + pos * 4, hi);
                sts32(sm + XL_OFF + (uint32_t)(r * 1024) + pos * 4, lo);
            }
        }
    }
    // (first __syncthreads happens inside gemm prologue — covers x fill too)

    const size_t wbase = (size_t)ch * Wn * Wn;
    float accA[32], accB[32];

    // ---- Q -> accA, K -> accB ----
    gemm_tf32(accA, qw + wbase, sm, tid, lane, wm, wn);
    gemm_tf32(accB, kw + wbase, sm, tid, lane, wm, wn);

    // ---- logits + softmax (registers + quad shfl + smem cross-warp) ----
    const int m = lane & 3, g = lane >> 2;
    const int r0 = wm * 16 + g;                  // local row (0..63)
    const int gr0 = h0 + r0;
    const size_t brow0 = ((size_t)(ch * Hn) + gr0) * Wn + wn * 64 + 2 * m;
    const size_t brow1 = brow0 + (size_t)8 * Wn;

    float mx0 = -3.4e38f, mx1 = -3.4e38f;
    #pragma unroll
    for (int nt = 0; nt < 8; ++nt) {
        float2 bq0 = *reinterpret_cast<const float2*>(qb + brow0 + nt * 8);
        float2 bq1 = *reinterpret_cast<const float2*>(qb + brow1 + nt * 8);
        float2 bk0 = *reinterpret_cast<const float2*>(kb + brow0 + nt * 8);
        float2 bk1 = *reinterpret_cast<const float2*>(kb + brow1 + nt * 8);
        float* A = accA + nt * 4; float* Bv = accB + nt * 4;
        Bv[0] = (A[0] + bq0.x) * (Bv[0] + bk0.x);
        Bv[1] = (A[1] + bq0.y) * (Bv[1] + bk0.y);
        Bv[2] = (A[2] + bq1.x) * (Bv[2] + bk1.x);
        Bv[3] = (A[3] + bq1.y) * (Bv[3] + bk1.y);
        mx0 = fmaxf(mx0, fmaxf(Bv[0], Bv[1]));
        mx1 = fmaxf(mx1, fmaxf(Bv[2], Bv[3]));
    }
    mx0 = fmaxf(mx0, __shfl_xor_sync(0xffffffffu, mx0, 1));
    mx0 = fmaxf(mx0, __shfl_xor_sync(0xffffffffu, mx0, 2));
    mx1 = fmaxf(mx1, __shfl_xor_sync(0xffffffffu, mx1, 1));
    mx1 = fmaxf(mx1, __shfl_xor_sync(0xffffffffu, mx1, 2));
    if (m == 0) { red[r0 * 8 + wn] = mx0; red[(r0 + 8) * 8 + wn] = mx1; }
    __syncthreads();
    {
        float4 a = *reinterpret_cast<float4*>(&red[r0 * 8]);
        float4 c = *reinterpret_cast<float4*>(&red[(r0 + 8) * 8]);
        mx0 = fmaxf(fmaxf(a.x, a.y), fmaxf(a.z, a.w));
        mx1 = fmaxf(fmaxf(c.x, c.y), fmaxf(c.z, c.w));
    }
    float s0 = 0.f, s1 = 0.f;
    #pragma unroll
    for (int nt = 0; nt < 8; ++nt) {
        float* Bv = accB + nt * 4;
        Bv[0] = __expf(Bv[0] - mx0); s0 += Bv[0];
        Bv[1] = __expf(Bv[1] - mx0); s0 += Bv[1];
        Bv[2] = __expf(Bv[2] - mx1); s1 += Bv[2];
        Bv[3] = __expf(Bv[3] - mx1); s1 += Bv[3];
    }
    s0 += __shfl_xor_sync(0xffffffffu, s0, 1);
    s0 += __shfl_xor_sync(0xffffffffu, s0, 2);
    s1 += __shfl_xor_sync(0xffffffffu, s1, 1);
    s1 += __shfl_xor_sync(0xffffffffu, s1, 2);
    if (m == 0) { red[r0 * 8 + 4 + wn] = s0; red[(r0 + 8) * 8 + 4 + wn] = s1; }
    __syncthreads();
    {
        float4 a = *reinterpret_cast<float4*>(&red[r0 * 8 + 4]);
        float4 c = *reinterpret_cast<float4*>(&red[(r0 + 8) * 8 + 4]);
        s0 = (a.x + a.y) + (a.z + a.w);
        s1 = (c.x + c.y) + (c.z + c.w);
    }
    const float r0i = 1.0f / s0, r1i = 1.0f / s1;
    #pragma unroll
    for (int nt = 0; nt < 8; ++nt) {
        accB[nt * 4 + 0] *= r0i; accB[nt * 4 + 1] *= r0i;
        accB[nt * 4 + 2] *= r1i; accB[nt * 4 + 3] *= r1i;
    }
    __syncthreads();   // red done; smem B-ring about to be reused

    // ---- V -> accA ----
    gemm_tf32(accA, vw + wbase, sm, tid, lane, wm, wn);

    // ---- out = P * (V + bv) ----
    {
        float* og0 = out + ((size_t)((b * Cn + ch) * Hn) + gr0) * Wn + wn * 64 + 2 * m;
        float* og1 = og0 + (size_t)8 * Wn;
        #pragma unroll
        for (int nt = 0; nt < 8; ++nt) {
            float2 bv0 = *reinterpret_cast<const float2*>(vb + brow0 + nt * 8);
            float2 bv1 = *reinterpret_cast<const float2*>(vb + brow1 + nt * 8);
            float* A = accA + nt * 4; float* P = accB + nt * 4;
            float2 o0, o1;
            o0.x = P[0] * (A[0] + bv0.x);
            o0.y = P[1] * (A[1] + bv0.y);
            o1.x = P[2] * (A[2] + bv1.x);
            o1.y = P[3] * (A[3] + bv1.y);
            *reinterpret_cast<float2*>(og0 + nt * 8) = o0;
            *reinterpret_cast<float2*>(og1 + nt * 8) = o1;
        }
    }
}

extern "C" void kernel_launch(void* const* d_in, const int* in_sizes, int n_in,
                              void* d_out, int out_size) {
    const float* x  = (const float*)d_in[0];
    const float* qw = (const float*)d_in[1];
    const float* kw = (const float*)d_in[2];
    const float* vw = (const float*)d_in[3];
    const float* qb = (const float*)d_in[4];
    const float* kb = (const float*)d_in[5];
    const float* vb = (const float*)d_in[6];
    float* out = (float*)d_out;

    cudaFuncSetAttribute(axile_attn_mma,
                         cudaFuncAttributeMaxDynamicSharedMemorySize, SM_TOTAL);
    dim3 grid(Hn / TM, Cn, Bn);   // 4 x 64 x 8 = 2048 CTAs
    axile_attn_mma<<<grid, NTH, SM_TOTAL>>>(x, qw, kw, vw, qb, kb, vb, out);
}

// round 8
// speedup vs baseline: 1.3585x; 1.3585x over previous
#include <cuda_runtime.h>
#include <cstdint>

#define Bn 8
#define Cn 64
#define Hn 256
#define Wn 256
#define TM 64
#define NTH 256
#define NCH 16

// smem byte offsets
#define XH_OFF 0          // x hi fp16 [64][256], swizzled rows (512B), 32KB
#define XL_OFF 32768      // x lo
#define B_OFF  65536      // 3 stages x 16KB: {HI:[kb2][n256][k8], LO at +8192}
#define B_STRIDE 16384
#define B_LO   8192
#define L_OFF  114688     // Ls f32 [64][256] swizzled, 64KB
#define R_OFF  180224     // red [64][8] f32
#define SM_TOTAL 182272

__device__ __forceinline__ uint32_t f2h(float f) {
    uint32_t r; asm("cvt.rn.f16.f32 %0,%1;" : "=r"(r) : "f"(f)); return r;
}
__device__ __forceinline__ float h2f(uint32_t h) {
    float r; asm("cvt.f32.f16 %0,%1;" : "=f"(r) : "r"(h)); return r;
}
__device__ __forceinline__ void sts128(uint32_t a, uint32_t x, uint32_t y, uint32_t z, uint32_t w) {
    asm volatile("st.shared.v4.b32 [%0],{%1,%2,%3,%4};" :: "r"(a), "r"(x), "r"(y), "r"(z), "r"(w));
}
__device__ __forceinline__ void sts64(uint32_t a, uint32_t x, uint32_t y) {
    asm volatile("st.shared.v2.b32 [%0],{%1,%2};" :: "r"(a), "r"(x), "r"(y));
}
__device__ __forceinline__ void stsf2(uint32_t a, float x, float y) {
    asm volatile("st.shared.v2.f32 [%0],{%1,%2};" :: "r"(a), "f"(x), "f"(y));
}
__device__ __forceinline__ float2 ldsf2(uint32_t a) {
    float2 r;
    asm volatile("ld.shared.v2.f32 {%0,%1},[%2];" : "=f"(r.x), "=f"(r.y) : "r"(a));
    return r;
}
__device__ __forceinline__ void ldmx4(uint32_t* r, uint32_t a) {
    asm volatile("ldmatrix.sync.aligned.m8n8.x4.shared.b16 {%0,%1,%2,%3},[%4];"
                 : "=r"(r[0]), "=r"(r[1]), "=r"(r[2]), "=r"(r[3]) : "r"(a));
}
__device__ __forceinline__ void mma16(float* c, const uint32_t* a, uint32_t b0, uint32_t b1) {
    asm volatile(
        "mma.sync.aligned.m16n8k16.row.col.f32.f16.f16.f32 "
        "{%0,%1,%2,%3},{%4,%5,%6,%7},{%8,%9},{%0,%1,%2,%3};"
        : "+f"(c[0]), "+f"(c[1]), "+f"(c[2]), "+f"(c[3])
        : "r"(a[0]), "r"(a[1]), "r"(a[2]), "r"(a[3]), "r"(b0), "r"(b1));
}
__device__ __forceinline__ uint32_t ls_addr(uint32_t sm, int r, int cb, int m) {
    return sm + L_OFF + (uint32_t)(r * 1024) +
           (uint32_t)((((cb >> 3) ^ (r & 7)) << 5) + m * 8);
}

// ---------------------------------------------------------------------------
// 64x256x256 GEMM, fp16 2-term split. acc[mt*32 + nt*4 + ci].
// Warp tile 32(rows) x 64(cols): wm in {0,1}, wn in {0..3}.
// ---------------------------------------------------------------------------
__device__ __forceinline__ void gemm_f16(float acc[64], const float* __restrict__ wg,
                                         uint32_t sm, int tid, int lane, int wm, int wn)
{
    #pragma unroll
    for (int i = 0; i < 64; ++i) acc[i] = 0.f;

    float rb[2][16];
    const int n = tid;

    auto LDGf = [&](float* rr, int cc) {
        const float* p = wg + (size_t)(cc * 16) * Wn + n;
        #pragma unroll
        for (int kk = 0; kk < 16; ++kk) rr[kk] = p[(size_t)kk * Wn];
    };
    auto STSf = [&](const float* rr, int cc) {
        const uint32_t bs = sm + B_OFF + (uint32_t)(cc % 3) * B_STRIDE;
        uint32_t hw[8], lw[8];
        #pragma unroll
        for (int q = 0; q < 8; ++q) {
            uint32_t h0 = f2h(rr[2*q]), h1 = f2h(rr[2*q+1]);
            uint32_t l0 = f2h(rr[2*q] - h2f(h0));
            uint32_t l1 = f2h(rr[2*q+1] - h2f(h1));
            hw[q] = h0 | (h1 << 16);
            lw[q] = l0 | (l1 << 16);
        }
        const uint32_t a0 = bs + (uint32_t)(n * 16);
        sts128(a0,                 hw[0], hw[1], hw[2], hw[3]);
        sts128(a0 + 4096,          hw[4], hw[5], hw[6], hw[7]);
        sts128(a0 + B_LO,          lw[0], lw[1], lw[2], lw[3]);
        sts128(a0 + B_LO + 4096,   lw[4], lw[5], lw[6], lw[7]);
    };

    LDGf(rb[0], 0);
    LDGf(rb[1], 1);
    STSf(rb[0], 0);
    __syncthreads();

    const int li = lane >> 3, lj = lane & 7;
    // A address pieces: r = wm*32 + mt*16 + (li&1)*8 + lj
    const uint32_t ar0 = (uint32_t)(wm * 32 + (li & 1) * 8 + lj);
    // B: lane offset within stage
    const uint32_t bo = (uint32_t)((li & 1) * 4096 +
                        ((wn * 64) + ((li >> 1) * 8) + lj) * 16);

    #pragma unroll 1
    for (int cc = 0; cc < NCH; ++cc) {
        if (cc + 2 < NCH) LDGf(rb[cc & 1], cc + 2);

        uint32_t ah[2][4], al[2][4];
        #pragma unroll
        for (int mt = 0; mt < 2; ++mt) {
            const uint32_t r = ar0 + mt * 16;
            const uint32_t aoff = r * 512 +
                ((uint32_t)((cc * 2 + (li >> 1)) * 16) ^ (uint32_t)(lj * 16));
            ldmx4(ah[mt], sm + XH_OFF + aoff);
            ldmx4(al[mt], sm + XL_OFF + aoff);
        }
        uint32_t bh[16], bl[16];
        {
            const uint32_t bs = sm + B_OFF + (uint32_t)(cc % 3) * B_STRIDE + bo;
            #pragma unroll
            for (int p = 0; p < 4; ++p) {
                ldmx4(&bh[p * 4], bs + p * 256);
                ldmx4(&bl[p * 4], bs + B_LO + p * 256);
            }
        }
        #pragma unroll
        for (int mt = 0; mt < 2; ++mt)
            #pragma unroll
            for (int nt = 0; nt < 8; ++nt) {
                float* a4 = acc + mt * 32 + nt * 4;
                mma16(a4, ah[mt], bh[nt * 2], bh[nt * 2 + 1]);
                mma16(a4, ah[mt], bl[nt * 2], bl[nt * 2 + 1]);
                mma16(a4, al[mt], bh[nt * 2], bh[nt * 2 + 1]);
            }

        if (cc + 1 < NCH) STSf(rb[(cc + 1) & 1], cc + 1);
        __syncthreads();
    }
}

extern __shared__ float smem_dyn[];

__global__ void __launch_bounds__(NTH, 1) axile_attn_f16(
    const float* __restrict__ x,  const float* __restrict__ qw,
    const float* __restrict__ kw, const float* __restrict__ vw,
    const float* __restrict__ qb, const float* __restrict__ kb,
    const float* __restrict__ vb, float* __restrict__ out)
{
    const int tid  = threadIdx.x;
    const int lane = tid & 31;
    const int wid  = tid >> 5;
    const int wm   = wid & 1;
    const int wn   = wid >> 1;
    const int m    = lane & 3;
    const int g    = lane >> 2;
    const int ht   = blockIdx.x & 3;
    const int b    = blockIdx.x >> 2;
    const int c    = blockIdx.y;
    const int h0   = ht * TM;

    const uint32_t sm = (uint32_t)__cvta_generic_to_shared(smem_dyn);
    float* red = reinterpret_cast<float*>(reinterpret_cast<char*>(smem_dyn) + R_OFF);

    // ---- fill x fp16 hi/lo planes ----
    {
        const float* xg = x + ((size_t)((b * Cn + c) * Hn + h0)) * Wn;
        #pragma unroll
        for (int it = 0; it < 16; ++it) {
            const int idx = tid + it * NTH;
            const int r = idx >> 6, j4 = idx & 63, k = j4 * 4;
            float4 v = reinterpret_cast<const float4*>(xg)[(size_t)r * 64 + j4];
            const float f[4] = {v.x, v.y, v.z, v.w};
            uint32_t h[4], lo[4];
            #pragma unroll
            for (int s = 0; s < 4; ++s) {
                h[s]  = f2h(f[s]);
                lo[s] = f2h(f[s] - h2f(h[s]));
            }
            const uint32_t a = sm + XH_OFF + (uint32_t)(r * 512) +
                (((uint32_t)((k >> 3) * 16)) ^ ((uint32_t)((r & 7) * 16))) +
                (uint32_t)((k & 4) * 2);
            sts64(a,                 h[0]  | (h[1]  << 16), h[2]  | (h[3]  << 16));
            sts64(a + (XL_OFF - XH_OFF), lo[0] | (lo[1] << 16), lo[2] | (lo[3] << 16));
        }
    }
    // first gemm's prologue __syncthreads covers visibility of x planes

    const size_t wbase = (size_t)c * Wn * Wn;
    float acc[64];

    // row/col geometry for epilogues
    const int rA0 = wm * 32 + g;               // mt0, low half
    const int cb0 = wn * 64;
    const size_t bias_row = ((size_t)c * Hn + h0) * Wn;

    // =============== Q gemm -> spill to Ls ===============
    gemm_f16(acc, qw + wbase, sm, tid, lane, wm, wn);
    #pragma unroll
    for (int mt = 0; mt < 2; ++mt)
        #pragma unroll
        for (int nt = 0; nt < 8; ++nt) {
            const int rA = rA0 + mt * 16, rB = rA + 8;
            const int cb = cb0 + nt * 8;
            const float* a4 = acc + mt * 32 + nt * 4;
            stsf2(ls_addr(sm, rA, cb, m), a4[0], a4[1]);
            stsf2(ls_addr(sm, rB, cb, m), a4[2], a4[3]);
        }

    // =============== K gemm -> logits -> softmax -> P in Ls ===============
    gemm_f16(acc, kw + wbase, sm, tid, lane, wm, wn);
    {
        float mx[4] = {-3.4e38f, -3.4e38f, -3.4e38f, -3.4e38f};
        #pragma unroll
        for (int mt = 0; mt < 2; ++mt)
            #pragma unroll
            for (int nt = 0; nt < 8; ++nt) {
                const int rA = rA0 + mt * 16, rB = rA + 8;
                const int cb = cb0 + nt * 8;
                float2 qA = ldsf2(ls_addr(sm, rA, cb, m));
                float2 qB = ldsf2(ls_addr(sm, rB, cb, m));
                const size_t ba = bias_row + (size_t)rA * Wn + cb + m * 2;
                const size_t bb = bias_row + (size_t)rB * Wn + cb + m * 2;
                float2 bqA = *reinterpret_cast<const float2*>(qb + ba);
                float2 bqB = *reinterpret_cast<const float2*>(qb + bb);
                float2 bkA = *reinterpret_cast<const float2*>(kb + ba);
                float2 bkB = *reinterpret_cast<const float2*>(kb + bb);
                float* a4 = acc + mt * 32 + nt * 4;
                a4[0] = (qA.x + bqA.x) * (a4[0] + bkA.x);
                a4[1] = (qA.y + bqA.y) * (a4[1] + bkA.y);
                a4[2] = (qB.x + bqB.x) * (a4[2] + bkB.x);
                a4[3] = (qB.y + bqB.y) * (a4[3] + bkB.y);
                mx[mt * 2 + 0] = fmaxf(mx[mt * 2 + 0], fmaxf(a4[0], a4[1]));
                mx[mt * 2 + 1] = fmaxf(mx[mt * 2 + 1], fmaxf(a4[2], a4[3]));
            }
        #pragma unroll
        for (int q = 0; q < 4; ++q) {
            mx[q] = fmaxf(mx[q], __shfl_xor_sync(0xffffffffu, mx[q], 1));
            mx[q] = fmaxf(mx[q], __shfl_xor_sync(0xffffffffu, mx[q], 2));
        }
        if (m == 0) {
            #pragma unroll
            for (int q = 0; q < 4; ++q) {
                const int r = rA0 + (q >> 1) * 16 + (q & 1) * 8;
                red[r * 8 + wn] = mx[q];
            }
        }
        __syncthreads();
        #pragma unroll
        for (int q = 0; q < 4; ++q) {
            const int r = rA0 + (q >> 1) * 16 + (q & 1) * 8;
            float4 v = *reinterpret_cast<float4*>(&red[r * 8]);
            mx[q] = fmaxf(fmaxf(v.x, v.y), fmaxf(v.z, v.w));
        }
        float sum[4] = {0.f, 0.f, 0.f, 0.f};
        #pragma unroll
        for (int mt = 0; mt < 2; ++mt)
            #pragma unroll
            for (int nt = 0; nt < 8; ++nt) {
                float* a4 = acc + mt * 32 + nt * 4;
                a4[0] = __expf(a4[0] - mx[mt * 2 + 0]); sum[mt * 2 + 0] += a4[0];
                a4[1] = __expf(a4[1] - mx[mt * 2 + 0]); sum[mt * 2 + 0] += a4[1];
                a4[2] = __expf(a4[2] - mx[mt * 2 + 1]); sum[mt * 2 + 1] += a4[2];
                a4[3] = __expf(a4[3] - mx[mt * 2 + 1]); sum[mt * 2 + 1] += a4[3];
            }
        #pragma unroll
        for (int q = 0; q < 4; ++q) {
            sum[q] += __shfl_xor_sync(0xffffffffu, sum[q], 1);
            sum[q] += __shfl_xor_sync(0xffffffffu, sum[q], 2);
        }
        if (m == 0) {
            #pragma unroll
            for (int q = 0; q < 4; ++q) {
                const int r = rA0 + (q >> 1) * 16 + (q & 1) * 8;
                red[r * 8 + 4 + wn] = sum[q];
            }
        }
        __syncthreads();
        float rinv[4];
        #pragma unroll
        for (int q = 0; q < 4; ++q) {
            const int r = rA0 + (q >> 1) * 16 + (q & 1) * 8;
            float4 v = *reinterpret_cast<float4*>(&red[r * 8 + 4]);
            rinv[q] = 1.0f / ((v.x + v.y) + (v.z + v.w));
        }
        #pragma unroll
        for (int mt = 0; mt < 2; ++mt)
            #pragma unroll
            for (int nt = 0; nt < 8; ++nt) {
                const int rA = rA0 + mt * 16, rB = rA + 8;
                const int cb = cb0 + nt * 8;
                float* a4 = acc + mt * 32 + nt * 4;
                stsf2(ls_addr(sm, rA, cb, m), a4[0] * rinv[mt * 2], a4[1] * rinv[mt * 2]);
                stsf2(ls_addr(sm, rB, cb, m), a4[2] * rinv[mt * 2 + 1], a4[3] * rinv[mt * 2 + 1]);
            }
    }

    // =============== V gemm -> out = P * (V + bv) ===============
    gemm_f16(acc, vw + wbase, sm, tid, lane, wm, wn);
    {
        float* og = out + ((size_t)((b * Cn + c) * Hn + h0)) * Wn;
        #pragma unroll
        for (int mt = 0; mt < 2; ++mt)
            #pragma unroll
            for (int nt = 0; nt < 8; ++nt) {
                const int rA = rA0 + mt * 16, rB = rA + 8;
                const int cb = cb0 + nt * 8;
                float2 pA = ldsf2(ls_addr(sm, rA, cb, m));
                float2 pB = ldsf2(ls_addr(sm, rB, cb, m));
                const size_t ba = bias_row + (size_t)rA * Wn + cb + m * 2;
                const size_t bb = bias_row + (size_t)rB * Wn + cb + m * 2;
                float2 bvA = *reinterpret_cast<const float2*>(vb + ba);
                float2 bvB = *reinterpret_cast<const float2*>(vb + bb);
                const float* a4 = acc + mt * 32 + nt * 4;
                float2 oA, oB;
                oA.x = pA.x * (a4[0] + bvA.x);
                oA.y = pA.y * (a4[1] + bvA.y);
                oB.x = pB.x * (a4[2] + bvB.x);
                oB.y = pB.y * (a4[3] + bvB.y);
                *reinterpret_cast<float2*>(og + (size_t)rA * Wn + cb + m * 2) = oA;
                *reinterpret_cast<float2*>(og + (size_t)rB * Wn + cb + m * 2) = oB;
            }
    }
}

extern "C" void kernel_launch(void* const* d_in, const int* in_sizes, int n_in,
                              void* d_out, int out_size) {
    const float* x  = (const float*)d_in[0];
    const float* qw = (const float*)d_in[1];
    const float* kw = (const float*)d_in[2];
    const float* vw = (const float*)d_in[3];
    const float* qb = (const float*)d_in[4];
    const float* kb = (const float*)d_in[5];
    const float* vb = (const float*)d_in[6];
    float* out = (float*)d_out;

    cudaFuncSetAttribute(axile_attn_f16,
                         cudaFuncAttributeMaxDynamicSharedMemorySize, SM_TOTAL);
    // grid.x = (htile, b) so CTAs sharing channel-c weights run concurrently
    dim3 grid((Hn / TM) * Bn, Cn);   // 32 x 64 = 2048 CTAs
    axile_attn_f16<<<grid, NTH, SM_TOTAL>>>(x, qw, kw, vw, qb, kb, vb, out);
}

// round 9
// speedup vs baseline: 1.6910x; 1.2448x over previous
#include <cuda_runtime.h>
#include <cstdint>

#define Bn 8
#define Cn 64
#define Hn 256
#define Wn 256
#define TM 64
#define NTH 512
#define NCH 16

// smem byte offsets
#define XH_OFF 0          // x hi fp16 [64][256], swizzled rows (512B), 32KB
#define XL_OFF 32768      // x lo
#define B_OFF  65536      // 3 stages x 16KB: {HI:[kh2][n256][k8], LO at +8192}
#define B_STRIDE 16384
#define B_LO   8192
#define L_OFF  114688     // Ls f32 [64][256] swizzled, 64KB
#define R_OFF  180224     // red [64][8] f32
#define SM_TOTAL 182272

__device__ __forceinline__ uint32_t f2h(float f) {
    uint32_t r; asm("cvt.rn.f16.f32 %0,%1;" : "=r"(r) : "f"(f)); return r;
}
__device__ __forceinline__ float h2f(uint32_t h) {
    float r; asm("cvt.f32.f16 %0,%1;" : "=f"(r) : "r"(h)); return r;
}
__device__ __forceinline__ void sts128(uint32_t a, uint32_t x, uint32_t y, uint32_t z, uint32_t w) {
    asm volatile("st.shared.v4.b32 [%0],{%1,%2,%3,%4};" :: "r"(a), "r"(x), "r"(y), "r"(z), "r"(w));
}
__device__ __forceinline__ void sts64(uint32_t a, uint32_t x, uint32_t y) {
    asm volatile("st.shared.v2.b32 [%0],{%1,%2};" :: "r"(a), "r"(x), "r"(y));
}
__device__ __forceinline__ void stsf2(uint32_t a, float x, float y) {
    asm volatile("st.shared.v2.f32 [%0],{%1,%2};" :: "r"(a), "f"(x), "f"(y));
}
__device__ __forceinline__ float2 ldsf2(uint32_t a) {
    float2 r;
    asm volatile("ld.shared.v2.f32 {%0,%1},[%2];" : "=f"(r.x), "=f"(r.y) : "r"(a));
    return r;
}
__device__ __forceinline__ void ldmx4(uint32_t* r, uint32_t a) {
    asm volatile("ldmatrix.sync.aligned.m8n8.x4.shared.b16 {%0,%1,%2,%3},[%4];"
                 : "=r"(r[0]), "=r"(r[1]), "=r"(r[2]), "=r"(r[3]) : "r"(a));
}
__device__ __forceinline__ void mma16(float* c, const uint32_t* a, uint32_t b0, uint32_t b1) {
    asm volatile(
        "mma.sync.aligned.m16n8k16.row.col.f32.f16.f16.f32 "
        "{%0,%1,%2,%3},{%4,%5,%6,%7},{%8,%9},{%0,%1,%2,%3};"
        : "+f"(c[0]), "+f"(c[1]), "+f"(c[2]), "+f"(c[3])
        : "r"(a[0]), "r"(a[1]), "r"(a[2]), "r"(a[3]), "r"(b0), "r"(b1));
}
__device__ __forceinline__ uint32_t ls_addr(uint32_t sm, int r, int cb, int m) {
    return sm + L_OFF + (uint32_t)(r * 1024) +
           (uint32_t)((((cb >> 3) ^ (r & 7)) << 5) + m * 8);
}

// ---------------------------------------------------------------------------
// 64x256x256 GEMM, fp16 2-term split. 16 warps: wm in {0..3}, wn in {0..3}.
// Warp tile 16(rows) x 64(cols). acc[nt*4 + ci].
// ---------------------------------------------------------------------------
__device__ __forceinline__ void gemm_f16(float acc[32], const float* __restrict__ wg,
                                         uint32_t sm, int tid, int lane, int wm, int wn)
{
    #pragma unroll
    for (int i = 0; i < 32; ++i) acc[i] = 0.f;

    float rb[2][8];
    const int nn = tid & 255;
    const int khalf = tid >> 8;            // 0 or 1: k octet within chunk

    auto LDGf = [&](float* rr, int cc) {
        const float* p = wg + (size_t)(cc * 16 + khalf * 8) * Wn + nn;
        #pragma unroll
        for (int j = 0; j < 8; ++j) rr[j] = p[(size_t)j * Wn];
    };
    auto STSf = [&](const float* rr, int cc) {
        const uint32_t bs = sm + B_OFF + (uint32_t)(cc % 3) * B_STRIDE;
        uint32_t hw[4], lw[4];
        #pragma unroll
        for (int q = 0; q < 4; ++q) {
            uint32_t h0 = f2h(rr[2*q]), h1 = f2h(rr[2*q+1]);
            uint32_t l0 = f2h(rr[2*q] - h2f(h0));
            uint32_t l1 = f2h(rr[2*q+1] - h2f(h1));
            hw[q] = h0 | (h1 << 16);
            lw[q] = l0 | (l1 << 16);
        }
        const uint32_t a0 = bs + (uint32_t)(khalf * 4096 + nn * 16);
        sts128(a0,        hw[0], hw[1], hw[2], hw[3]);
        sts128(a0 + B_LO, lw[0], lw[1], lw[2], lw[3]);
    };

    LDGf(rb[0], 0);
    LDGf(rb[1], 1);
    STSf(rb[0], 0);
    __syncthreads();

    const int li = lane >> 3, lj = lane & 7;
    const uint32_t ar0 = (uint32_t)(wm * 16 + (li & 1) * 8 + lj);
    const uint32_t bo = (uint32_t)((li & 1) * 4096 +
                        ((wn * 64) + ((li >> 1) * 8) + lj) * 16);

    #pragma unroll 1
    for (int cc = 0; cc < NCH; ++cc) {
        if (cc + 2 < NCH) LDGf(rb[cc & 1], cc + 2);

        uint32_t ah[4], al[4];
        {
            const uint32_t aoff = ar0 * 512 +
                ((uint32_t)((cc * 2 + (li >> 1)) * 16) ^ (uint32_t)(lj * 16));
            ldmx4(ah, sm + XH_OFF + aoff);
            ldmx4(al, sm + XL_OFF + aoff);
        }
        uint32_t bh[16], bl[16];
        {
            const uint32_t bs = sm + B_OFF + (uint32_t)(cc % 3) * B_STRIDE + bo;
            #pragma unroll
            for (int p = 0; p < 4; ++p) {
                ldmx4(&bh[p * 4], bs + p * 256);
                ldmx4(&bl[p * 4], bs + B_LO + p * 256);
            }
        }
        #pragma unroll
        for (int nt = 0; nt < 8; ++nt) {
            float* a4 = acc + nt * 4;
            mma16(a4, ah, bh[nt * 2], bh[nt * 2 + 1]);
            mma16(a4, ah, bl[nt * 2], bl[nt * 2 + 1]);
            mma16(a4, al, bh[nt * 2], bh[nt * 2 + 1]);
        }

        if (cc + 1 < NCH) STSf(rb[(cc + 1) & 1], cc + 1);
        __syncthreads();
    }
}

extern __shared__ float smem_dyn[];

__global__ void __launch_bounds__(NTH, 1) axile_attn_f16(
    const float* __restrict__ x,  const float* __restrict__ qw,
    const float* __restrict__ kw, const float* __restrict__ vw,
    const float* __restrict__ qb, const float* __restrict__ kb,
    const float* __restrict__ vb, float* __restrict__ out)
{
    const int tid  = threadIdx.x;
    const int lane = tid & 31;
    const int wid  = tid >> 5;
    const int wm   = wid & 3;
    const int wn   = wid >> 2;
    const int m    = lane & 3;
    const int g    = lane >> 2;
    const int ht   = blockIdx.x & 3;
    const int b    = blockIdx.x >> 2;
    const int c    = blockIdx.y;
    const int h0   = ht * TM;

    const uint32_t sm = (uint32_t)__cvta_generic_to_shared(smem_dyn);
    float* red = reinterpret_cast<float*>(reinterpret_cast<char*>(smem_dyn) + R_OFF);

    // ---- fill x fp16 hi/lo planes ----
    {
        const float* xg = x + ((size_t)((b * Cn + c) * Hn + h0)) * Wn;
        #pragma unroll
        for (int it = 0; it < 8; ++it) {
            const int idx = tid + it * NTH;
            const int r = idx >> 6, j4 = idx & 63, k = j4 * 4;
            float4 v = reinterpret_cast<const float4*>(xg)[(size_t)r * 64 + j4];
            const float f[4] = {v.x, v.y, v.z, v.w};
            uint32_t h[4], lo[4];
            #pragma unroll
            for (int s = 0; s < 4; ++s) {
                h[s]  = f2h(f[s]);
                lo[s] = f2h(f[s] - h2f(h[s]));
            }
            const uint32_t a = sm + XH_OFF + (uint32_t)(r * 512) +
                (((uint32_t)((k >> 3) * 16)) ^ ((uint32_t)((r & 7) * 16))) +
                (uint32_t)((k & 4) * 2);
            sts64(a,                     h[0]  | (h[1]  << 16), h[2]  | (h[3]  << 16));
            sts64(a + (XL_OFF - XH_OFF), lo[0] | (lo[1] << 16), lo[2] | (lo[3] << 16));
        }
    }
    // first gemm's prologue __syncthreads covers visibility of x planes

    const size_t wbase = (size_t)c * Wn * Wn;
    float acc[32];

    const int rA0 = wm * 16 + g;               // low row; high row = rA0 + 8
    const int cb0 = wn * 64;
    const size_t bias_row = ((size_t)c * Hn + h0) * Wn;

    // =============== Q gemm -> spill to Ls ===============
    gemm_f16(acc, qw + wbase, sm, tid, lane, wm, wn);
    #pragma unroll
    for (int nt = 0; nt < 8; ++nt) {
        const int rA = rA0, rB = rA0 + 8;
        const int cb = cb0 + nt * 8;
        const float* a4 = acc + nt * 4;
        stsf2(ls_addr(sm, rA, cb, m), a4[0], a4[1]);
        stsf2(ls_addr(sm, rB, cb, m), a4[2], a4[3]);
    }

    // =============== K gemm -> logits -> softmax -> P in Ls ===============
    gemm_f16(acc, kw + wbase, sm, tid, lane, wm, wn);
    {
        float mx[2] = {-3.4e38f, -3.4e38f};
        #pragma unroll
        for (int nt = 0; nt < 8; ++nt) {
            const int rA = rA0, rB = rA0 + 8;
            const int cb = cb0 + nt * 8;
            float2 qA = ldsf2(ls_addr(sm, rA, cb, m));
            float2 qB = ldsf2(ls_addr(sm, rB, cb, m));
            const size_t ba = bias_row + (size_t)rA * Wn + cb + m * 2;
            const size_t bb = bias_row + (size_t)rB * Wn + cb + m * 2;
            float2 bqA = *reinterpret_cast<const float2*>(qb + ba);
            float2 bqB = *reinterpret_cast<const float2*>(qb + bb);
            float2 bkA = *reinterpret_cast<const float2*>(kb + ba);
            float2 bkB = *reinterpret_cast<const float2*>(kb + bb);
            float* a4 = acc + nt * 4;
            a4[0] = (qA.x + bqA.x) * (a4[0] + bkA.x);
            a4[1] = (qA.y + bqA.y) * (a4[1] + bkA.y);
            a4[2] = (qB.x + bqB.x) * (a4[2] + bkB.x);
            a4[3] = (qB.y + bqB.y) * (a4[3] + bkB.y);
            mx[0] = fmaxf(mx[0], fmaxf(a4[0], a4[1]));
            mx[1] = fmaxf(mx[1], fmaxf(a4[2], a4[3]));
        }
        #pragma unroll
        for (int q = 0; q < 2; ++q) {
            mx[q] = fmaxf(mx[q], __shfl_xor_sync(0xffffffffu, mx[q], 1));
            mx[q] = fmaxf(mx[q], __shfl_xor_sync(0xffffffffu, mx[q], 2));
        }
        if (m == 0) {
            red[rA0 * 8 + wn]       = mx[0];
            red[(rA0 + 8) * 8 + wn] = mx[1];
        }
        __syncthreads();
        {
            float4 v0 = *reinterpret_cast<float4*>(&red[rA0 * 8]);
            float4 v1 = *reinterpret_cast<float4*>(&red[(rA0 + 8) * 8]);
            mx[0] = fmaxf(fmaxf(v0.x, v0.y), fmaxf(v0.z, v0.w));
            mx[1] = fmaxf(fmaxf(v1.x, v1.y), fmaxf(v1.z, v1.w));
        }
        float sum[2] = {0.f, 0.f};
        #pragma unroll
        for (int nt = 0; nt < 8; ++nt) {
            float* a4 = acc + nt * 4;
            a4[0] = __expf(a4[0] - mx[0]); sum[0] += a4[0];
            a4[1] = __expf(a4[1] - mx[0]); sum[0] += a4[1];
            a4[2] = __expf(a4[2] - mx[1]); sum[1] += a4[2];
            a4[3] = __expf(a4[3] - mx[1]); sum[1] += a4[3];
        }
        #pragma unroll
        for (int q = 0; q < 2; ++q) {
            sum[q] += __shfl_xor_sync(0xffffffffu, sum[q], 1);
            sum[q] += __shfl_xor_sync(0xffffffffu, sum[q], 2);
        }
        if (m == 0) {
            red[rA0 * 8 + 4 + wn]       = sum[0];
            red[(rA0 + 8) * 8 + 4 + wn] = sum[1];
        }
        __syncthreads();
        float rinv[2];
        {
            float4 v0 = *reinterpret_cast<float4*>(&red[rA0 * 8 + 4]);
            float4 v1 = *reinterpret_cast<float4*>(&red[(rA0 + 8) * 8 + 4]);
            rinv[0] = 1.0f / ((v0.x + v0.y) + (v0.z + v0.w));
            rinv[1] = 1.0f / ((v1.x + v1.y) + (v1.z + v1.w));
        }
        #pragma unroll
        for (int nt = 0; nt < 8; ++nt) {
            const int cb = cb0 + nt * 8;
            float* a4 = acc + nt * 4;
            stsf2(ls_addr(sm, rA0, cb, m),     a4[0] * rinv[0], a4[1] * rinv[0]);
            stsf2(ls_addr(sm, rA0 + 8, cb, m), a4[2] * rinv[1], a4[3] * rinv[1]);
        }
    }

    // =============== V gemm -> out = P * (V + bv) ===============
    gemm_f16(acc, vw + wbase, sm, tid, lane, wm, wn);
    {
        float* og = out + ((size_t)((b * Cn + c) * Hn + h0)) * Wn;
        #pragma unroll
        for (int nt = 0; nt < 8; ++nt) {
            const int rA = rA0, rB = rA0 + 8;
            const int cb = cb0 + nt * 8;
            float2 pA = ldsf2(ls_addr(sm, rA, cb, m));
            float2 pB = ldsf2(ls_addr(sm, rB, cb, m));
            const size_t ba = bias_row + (size_t)rA * Wn + cb + m * 2;
            const size_t bb = bias_row + (size_t)rB * Wn + cb + m * 2;
            float2 bvA = *reinterpret_cast<const float2*>(vb + ba);
            float2 bvB = *reinterpret_cast<const float2*>(vb + bb);
            const float* a4 = acc + nt * 4;
            float2 oA, oB;
            oA.x = pA.x * (a4[0] + bvA.x);
            oA.y = pA.y * (a4[1] + bvA.y);
            oB.x = pB.x * (a4[2] + bvB.x);
            oB.y = pB.y * (a4[3] + bvB.y);
            *reinterpret_cast<float2*>(og + (size_t)rA * Wn + cb + m * 2) = oA;
            *reinterpret_cast<float2*>(og + (size_t)rB * Wn + cb + m * 2) = oB;
        }
    }
}

extern "C" void kernel_launch(void* const* d_in, const int* in_sizes, int n_in,
                              void* d_out, int out_size) {
    const float* x  = (const float*)d_in[0];
    const float* qw = (const float*)d_in[1];
    const float* kw = (const float*)d_in[2];
    const float* vw = (const float*)d_in[3];
    const float* qb = (const float*)d_in[4];
    const float* kb = (const float*)d_in[5];
    const float* vb = (const float*)d_in[6];
    float* out = (float*)d_out;

    cudaFuncSetAttribute(axile_attn_f16,
                         cudaFuncAttributeMaxDynamicSharedMemorySize, SM_TOTAL);
    dim3 grid((Hn / TM) * Bn, Cn);   // 32 x 64 = 2048 CTAs
    axile_attn_f16<<<grid, NTH, SM_TOTAL>>>(x, qw, kw, vw, qb, kb, vb, out);
}

// round 10
// speedup vs baseline: 2.4838x; 1.4688x over previous
#include <cuda_runtime.h>
#include <cstdint>

#define Bn 8
#define Cn 64
#define Hn 256
#define Wn 256
#define TM 64
#define NTH 512
#define NCH 16

// main-kernel smem byte offsets
#define XH_OFF 0          // x hi fp16 [64][256], swizzled rows (512B), 32KB
#define XL_OFF 32768      // x lo
#define B_OFF  65536      // 4-stage ring, 16KB/stage: {HI:[kh2][n256][k8], LO at +8192}
#define B_STAGE 16384
#define B_LO   8192
#define L_OFF  131072     // Ls f32 [64][256] swizzled, 64KB
#define R_OFF  196608     // red [64][8] f32
#define SM_TOTAL 198656

// Pre-split fp16 weight planes: [which(3)][c(64)][chunk(16)][16KB stage image]
__device__ __align__(16) char g_wsplit[3ULL * 64 * 16 * 16384];

__device__ __forceinline__ uint32_t f2h(float f) {
    uint32_t r; asm("cvt.rn.f16.f32 %0,%1;" : "=r"(r) : "f"(f)); return r;
}
__device__ __forceinline__ float h2f(uint32_t h) {
    float r; asm("cvt.f32.f16 %0,%1;" : "=f"(r) : "r"(h)); return r;
}
__device__ __forceinline__ void sts64(uint32_t a, uint32_t x, uint32_t y) {
    asm volatile("st.shared.v2.b32 [%0],{%1,%2};" :: "r"(a), "r"(x), "r"(y));
}
__device__ __forceinline__ void stsf2(uint32_t a, float x, float y) {
    asm volatile("st.shared.v2.f32 [%0],{%1,%2};" :: "r"(a), "f"(x), "f"(y));
}
__device__ __forceinline__ float2 ldsf2(uint32_t a) {
    float2 r;
    asm volatile("ld.shared.v2.f32 {%0,%1},[%2];" : "=f"(r.x), "=f"(r.y) : "r"(a));
    return r;
}
__device__ __forceinline__ void ldmx4(uint32_t* r, uint32_t a) {
    asm volatile("ldmatrix.sync.aligned.m8n8.x4.shared.b16 {%0,%1,%2,%3},[%4];"
                 : "=r"(r[0]), "=r"(r[1]), "=r"(r[2]), "=r"(r[3]) : "r"(a));
}
__device__ __forceinline__ void mma16(float* c, const uint32_t* a, uint32_t b0, uint32_t b1) {
    asm volatile(
        "mma.sync.aligned.m16n8k16.row.col.f32.f16.f16.f32 "
        "{%0,%1,%2,%3},{%4,%5,%6,%7},{%8,%9},{%0,%1,%2,%3};"
        : "+f"(c[0]), "+f"(c[1]), "+f"(c[2]), "+f"(c[3])
        : "r"(a[0]), "r"(a[1]), "r"(a[2]), "r"(a[3]), "r"(b0), "r"(b1));
}
__device__ __forceinline__ void cp_async16(uint32_t dst, const void* src) {
    asm volatile("cp.async.cg.shared.global [%0], [%1], 16;" :: "r"(dst), "l"(src));
}
__device__ __forceinline__ uint32_t ls_addr(uint32_t sm, int r, int cb, int m) {
    return sm + L_OFF + (uint32_t)(r * 1024) +
           (uint32_t)((((cb >> 3) ^ (r & 7)) << 5) + m * 8);
}

// ===========================================================================
// Weight pre-split kernel: W[c] fp32 [k][n] -> per-chunk stage image
//   hi[kh][n][j] fp16 at offset (kh*256+n)*16 + j*2 ; lo plane at +8192
// ===========================================================================
__global__ void __launch_bounds__(256) wsplit_kernel(
    const float* __restrict__ qw, const float* __restrict__ kw,
    const float* __restrict__ vw)
{
    __shared__ float tile[16][260];
    const int cc = blockIdx.x;         // chunk
    const int c  = blockIdx.y;         // channel
    const int z  = blockIdx.z;         // which weight
    const int tid = threadIdx.x;

    const float* wsrc = (z == 0) ? qw : (z == 1) ? kw : vw;
    const float* wp = wsrc + (size_t)c * Wn * Wn + (size_t)cc * 16 * Wn;

    #pragma unroll
    for (int i = 0; i < 4; ++i) {
        const int idx = tid + i * 256;          // float4 index over 16x256 tile
        const int r = idx >> 6, c4 = idx & 63;
        float4 v = reinterpret_cast<const float4*>(wp + (size_t)r * Wn)[c4];
        *reinterpret_cast<float4*>(&tile[r][c4 * 4]) = v;
    }
    __syncthreads();

    char* dst = g_wsplit + (((size_t)z * 64 + c) * 16 + cc) * 16384;
    #pragma unroll
    for (int i = 0; i < 4; ++i) {
        const int o = tid + i * 256;            // uint4 slot 0..1023
        const int plane = o >> 9, rem = o & 511;
        const int kh = rem >> 8, n = rem & 255;
        uint32_t w[4];
        #pragma unroll
        for (int q = 0; q < 4; ++q) {
            float f0 = tile[kh * 8 + 2 * q][n];
            float f1 = tile[kh * 8 + 2 * q + 1][n];
            uint32_t h0 = f2h(f0), h1 = f2h(f1);
            if (plane) {
                h0 = f2h(f0 - h2f(h0));
                h1 = f2h(f1 - h2f(h1));
            }
            w[q] = h0 | (h1 << 16);
        }
        reinterpret_cast<uint4*>(dst)[o] = make_uint4(w[0], w[1], w[2], w[3]);
    }
}

// ===========================================================================
// 64x256x256 GEMM, fp16 2-term split, pre-split weights via cp.async.
// 16 warps: wm in {0,1} (32 rows), wn in {0..7} (32 cols). acc[mt*16+nt*4+ci].
// ===========================================================================
__device__ __forceinline__ void gemm_f16(float acc[32], const char* __restrict__ ws_src,
                                         uint32_t sm, int tid, int lane, int wm, int wn)
{
    #pragma unroll
    for (int i = 0; i < 32; ++i) acc[i] = 0.f;

    auto ISSUE = [&](int cc) {
        const char* src = ws_src + (size_t)cc * 16384 + tid * 32;
        const uint32_t dst = sm + B_OFF + (uint32_t)((cc & 3) * B_STAGE + tid * 32);
        cp_async16(dst, src);
        cp_async16(dst + 16, src + 16);
        asm volatile("cp.async.commit_group;");
    };

    ISSUE(0); ISSUE(1); ISSUE(2);

    const int li = lane >> 3, lj = lane & 7;
    const uint32_t ar0 = (uint32_t)(wm * 32 + (li & 1) * 8 + lj);
    const uint32_t bo = (uint32_t)((li & 1) * 4096 +
                        ((wn * 32) + ((li >> 1) * 8) + lj) * 16);

    #pragma unroll 1
    for (int cc = 0; cc < NCH; ++cc) {
        if (cc < NCH - 2)      asm volatile("cp.async.wait_group 2;");
        else if (cc == NCH - 2) asm volatile("cp.async.wait_group 1;");
        else                   asm volatile("cp.async.wait_group 0;");
        __syncthreads();
        if (cc + 3 < NCH) ISSUE(cc + 3);

        uint32_t ah[2][4], al[2][4];
        #pragma unroll
        for (int mt = 0; mt < 2; ++mt) {
            const uint32_t aoff = (ar0 + mt * 16) * 512 +
                ((uint32_t)((cc * 2 + (li >> 1)) * 16) ^ (uint32_t)(lj * 16));
            ldmx4(ah[mt], sm + XH_OFF + aoff);
            ldmx4(al[mt], sm + XL_OFF + aoff);
        }
        uint32_t bh[8], bl[8];
        {
            const uint32_t bs = sm + B_OFF + (uint32_t)((cc & 3) * B_STAGE) + bo;
            ldmx4(&bh[0], bs);
            ldmx4(&bh[4], bs + 256);
            ldmx4(&bl[0], bs + B_LO);
            ldmx4(&bl[4], bs + B_LO + 256);
        }
        #pragma unroll
        for (int mt = 0; mt < 2; ++mt)
            #pragma unroll
            for (int nt = 0; nt < 4; ++nt) {
                float* a4 = acc + mt * 16 + nt * 4;
                mma16(a4, ah[mt], bh[nt * 2], bh[nt * 2 + 1]);
                mma16(a4, ah[mt], bl[nt * 2], bl[nt * 2 + 1]);
                mma16(a4, al[mt], bh[nt * 2], bh[nt * 2 + 1]);
            }
    }
    __syncthreads();
}

extern __shared__ float smem_dyn[];

__global__ void __launch_bounds__(NTH, 1) axile_attn_f16(
    const float* __restrict__ x,
    const float* __restrict__ qb, const float* __restrict__ kb,
    const float* __restrict__ vb, float* __restrict__ out)
{
    const int tid  = threadIdx.x;
    const int lane = tid & 31;
    const int wid  = tid >> 5;
    const int wm   = wid & 1;
    const int wn   = wid >> 1;
    const int m    = lane & 3;
    const int g    = lane >> 2;
    const int ht   = blockIdx.x & 3;
    const int b    = blockIdx.x >> 2;
    const int c    = blockIdx.y;
    const int h0   = ht * TM;

    const uint32_t sm = (uint32_t)__cvta_generic_to_shared(smem_dyn);
    float* red = reinterpret_cast<float*>(reinterpret_cast<char*>(smem_dyn) + R_OFF);

    // ---- fill x fp16 hi/lo planes ----
    {
        const float* xg = x + ((size_t)((b * Cn + c) * Hn + h0)) * Wn;
        #pragma unroll
        for (int it = 0; it < 8; ++it) {
            const int idx = tid + it * NTH;
            const int r = idx >> 6, j4 = idx & 63, k = j4 * 4;
            float4 v = reinterpret_cast<const float4*>(xg)[(size_t)r * 64 + j4];
            const float f[4] = {v.x, v.y, v.z, v.w};
            uint32_t h[4], lo[4];
            #pragma unroll
            for (int s = 0; s < 4; ++s) {
                h[s]  = f2h(f[s]);
                lo[s] = f2h(f[s] - h2f(h[s]));
            }
            const uint32_t a = sm + XH_OFF + (uint32_t)(r * 512) +
                (((uint32_t)((k >> 3) * 16)) ^ ((uint32_t)((r & 7) * 16))) +
                (uint32_t)((k & 4) * 2);
            sts64(a,                     h[0]  | (h[1]  << 16), h[2]  | (h[3]  << 16));
            sts64(a + (XL_OFF - XH_OFF), lo[0] | (lo[1] << 16), lo[2] | (lo[3] << 16));
        }
    }
    // first gemm's first barrier covers x visibility

    const char* wq = g_wsplit + ((size_t)(0 * 64 + c)) * (16 * 16384);
    const char* wk = g_wsplit + ((size_t)(1 * 64 + c)) * (16 * 16384);
    const char* wv = g_wsplit + ((size_t)(2 * 64 + c)) * (16 * 16384);

    float acc[32];
    const int rAb = wm * 32 + g;              // + mt*16 (+8)
    const int cb0 = wn * 32;
    const size_t bias_row = ((size_t)c * Hn + h0) * Wn;

    // =============== Q gemm -> spill to Ls ===============
    gemm_f16(acc, wq, sm, tid, lane, wm, wn);
    #pragma unroll
    for (int mt = 0; mt < 2; ++mt)
        #pragma unroll
        for (int nt = 0; nt < 4; ++nt) {
            const int rA = rAb + mt * 16, rB = rA + 8;
            const int cb = cb0 + nt * 8;
            const float* a4 = acc + mt * 16 + nt * 4;
            stsf2(ls_addr(sm, rA, cb, m), a4[0], a4[1]);
            stsf2(ls_addr(sm, rB, cb, m), a4[2], a4[3]);
        }

    // =============== K gemm -> logits -> softmax -> P in Ls ===============
    gemm_f16(acc, wk, sm, tid, lane, wm, wn);
    {
        float mx[4] = {-3.4e38f, -3.4e38f, -3.4e38f, -3.4e38f};
        #pragma unroll
        for (int mt = 0; mt < 2; ++mt)
            #pragma unroll
            for (int nt = 0; nt < 4; ++nt) {
                const int rA = rAb + mt * 16, rB = rA + 8;
                const int cb = cb0 + nt * 8;
                float2 qA = ldsf2(ls_addr(sm, rA, cb, m));
                float2 qB = ldsf2(ls_addr(sm, rB, cb, m));
                const size_t ba = bias_row + (size_t)rA * Wn + cb + m * 2;
                const size_t bbo = bias_row + (size_t)rB * Wn + cb + m * 2;
                float2 bqA = *reinterpret_cast<const float2*>(qb + ba);
                float2 bqB = *reinterpret_cast<const float2*>(qb + bbo);
                float2 bkA = *reinterpret_cast<const float2*>(kb + ba);
                float2 bkB = *reinterpret_cast<const float2*>(kb + bbo);
                float* a4 = acc + mt * 16 + nt * 4;
                a4[0] = (qA.x + bqA.x) * (a4[0] + bkA.x);
                a4[1] = (qA.y + bqA.y) * (a4[1] + bkA.y);
                a4[2] = (qB.x + bqB.x) * (a4[2] + bkB.x);
                a4[3] = (qB.y + bqB.y) * (a4[3] + bkB.y);
                mx[mt * 2 + 0] = fmaxf(mx[mt * 2 + 0], fmaxf(a4[0], a4[1]));
                mx[mt * 2 + 1] = fmaxf(mx[mt * 2 + 1], fmaxf(a4[2], a4[3]));
            }
        #pragma unroll
        for (int q = 0; q < 4; ++q) {
            mx[q] = fmaxf(mx[q], __shfl_xor_sync(0xffffffffu, mx[q], 1));
            mx[q] = fmaxf(mx[q], __shfl_xor_sync(0xffffffffu, mx[q], 2));
        }
        if (m == 0) {
            #pragma unroll
            for (int q = 0; q < 4; ++q) {
                const int r = rAb + (q >> 1) * 16 + (q & 1) * 8;
                red[r * 8 + wn] = mx[q];
            }
        }
        __syncthreads();
        #pragma unroll
        for (int q = 0; q < 4; ++q) {
            const int r = rAb + (q >> 1) * 16 + (q & 1) * 8;
            float4 v0 = *reinterpret_cast<float4*>(&red[r * 8]);
            float4 v1 = *reinterpret_cast<float4*>(&red[r * 8 + 4]);
            mx[q] = fmaxf(fmaxf(fmaxf(v0.x, v0.y), fmaxf(v0.z, v0.w)),
                          fmaxf(fmaxf(v1.x, v1.y), fmaxf(v1.z, v1.w)));
        }
        __syncthreads();   // red reused for sums
        float sum[4] = {0.f, 0.f, 0.f, 0.f};
        #pragma unroll
        for (int mt = 0; mt < 2; ++mt)
            #pragma unroll
            for (int nt = 0; nt < 4; ++nt) {
                float* a4 = acc + mt * 16 + nt * 4;
                a4[0] = __expf(a4[0] - mx[mt * 2 + 0]); sum[mt * 2 + 0] += a4[0];
                a4[1] = __expf(a4[1] - mx[mt * 2 + 0]); sum[mt * 2 + 0] += a4[1];
                a4[2] = __expf(a4[2] - mx[mt * 2 + 1]); sum[mt * 2 + 1] += a4[2];
                a4[3] = __expf(a4[3] - mx[mt * 2 + 1]); sum[mt * 2 + 1] += a4[3];
            }
        #pragma unroll
        for (int q = 0; q < 4; ++q) {
            sum[q] += __shfl_xor_sync(0xffffffffu, sum[q], 1);
            sum[q] += __shfl_xor_sync(0xffffffffu, sum[q], 2);
        }
        if (m == 0) {
            #pragma unroll
            for (int q = 0; q < 4; ++q) {
                const int r = rAb + (q >> 1) * 16 + (q & 1) * 8;
                red[r * 8 + wn] = sum[q];
            }
        }
        __syncthreads();
        float rinv[4];
        #pragma unroll
        for (int q = 0; q < 4; ++q) {
            const int r = rAb + (q >> 1) * 16 + (q & 1) * 8;
            float4 v0 = *reinterpret_cast<float4*>(&red[r * 8]);
            float4 v1 = *reinterpret_cast<float4*>(&red[r * 8 + 4]);
            rinv[q] = 1.0f / (((v0.x + v0.y) + (v0.z + v0.w)) +
                              ((v1.x + v1.y) + (v1.z + v1.w)));
        }
        #pragma unroll
        for (int mt = 0; mt < 2; ++mt)
            #pragma unroll
            for (int nt = 0; nt < 4; ++nt) {
                const int rA = rAb + mt * 16, rB = rA + 8;
                const int cb = cb0 + nt * 8;
                float* a4 = acc + mt * 16 + nt * 4;
                stsf2(ls_addr(sm, rA, cb, m), a4[0] * rinv[mt * 2], a4[1] * rinv[mt * 2]);
                stsf2(ls_addr(sm, rB, cb, m), a4[2] * rinv[mt * 2 + 1], a4[3] * rinv[mt * 2 + 1]);
            }
    }

    // =============== V gemm -> out = P * (V + bv) ===============
    gemm_f16(acc, wv, sm, tid, lane, wm, wn);
    {
        float* og = out + ((size_t)((b * Cn + c) * Hn + h0)) * Wn;
        #pragma unroll
        for (int mt = 0; mt < 2; ++mt)
            #pragma unroll
            for (int nt = 0; nt < 4; ++nt) {
                const int rA = rAb + mt * 16, rB = rA + 8;
                const int cb = cb0 + nt * 8;
                float2 pA = ldsf2(ls_addr(sm, rA, cb, m));
                float2 pB = ldsf2(ls_addr(sm, rB, cb, m));
                const size_t ba = bias_row + (size_t)rA * Wn + cb + m * 2;
                const size_t bbo = bias_row + (size_t)rB * Wn + cb + m * 2;
                float2 bvA = *reinterpret_cast<const float2*>(vb + ba);
                float2 bvB = *reinterpret_cast<const float2*>(vb + bbo);
                const float* a4 = acc + mt * 16 + nt * 4;
                float2 oA, oB;
                oA.x = pA.x * (a4[0] + bvA.x);
                oA.y = pA.y * (a4[1] + bvA.y);
                oB.x = pB.x * (a4[2] + bvB.x);
                oB.y = pB.y * (a4[3] + bvB.y);
                *reinterpret_cast<float2*>(og + (size_t)rA * Wn + cb + m * 2) = oA;
                *reinterpret_cast<float2*>(og + (size_t)rB * Wn + cb + m * 2) = oB;
            }
    }
}

extern "C" void kernel_launch(void* const* d_in, const int* in_sizes, int n_in,
                              void* d_out, int out_size) {
    const float* x  = (const float*)d_in[0];
    const float* qw = (const float*)d_in[1];
    const float* kw = (const float*)d_in[2];
    const float* vw = (const float*)d_in[3];
    const float* qb = (const float*)d_in[4];
    const float* kb = (const float*)d_in[5];
    const float* vb = (const float*)d_in[6];
    float* out = (float*)d_out;

    // 1) pre-split weights into fp16 hi/lo stage images
    wsplit_kernel<<<dim3(16, 64, 3), 256>>>(qw, kw, vw);

    // 2) main fused kernel
    cudaFuncSetAttribute(axile_attn_f16,
                         cudaFuncAttributeMaxDynamicSharedMemorySize, SM_TOTAL);
    dim3 grid((Hn / TM) * Bn, Cn);   // 32 x 64 = 2048 CTAs
    axile_attn_f16<<<grid, NTH, SM_TOTAL>>>(x, qb, kb, vb, out);
}